// round 1
// baseline (speedup 1.0000x reference)
#include <cuda_runtime.h>
#include <math.h>

#define HH 48
#define WW 48
#define DD 64
#define BB 4
#define PP (HH*WW)        /* 2304 pixels */
#define CI 46
#define NJ (CI*CI)        /* 2116 interior candidates */
#define TEMPF 50.0f

// ---------------- scratch (device globals; no allocation allowed) ----------------
__device__ float g_bg [BB*PP*DD];                 // masked input  (2.36 MB)
__device__ float g_sg [BB*PP];                    // per-pixel sum g^2
__device__ float g_sbg[BB*PP];                    // per-pixel sum bg^2
__device__ float g_k1d[BB*NJ];
__device__ float g_wwd[BB*PP];
__device__ float g_C0 [(size_t)BB*PP*PP];         // g_in . bg^T   (85 MB)
__device__ float g_CA [(size_t)BB*PP*NJ];         // softmax attention (78 MB)
__device__ float g_E  [(size_t)BB*PP*PP];         // diag box-sum of scattered CA (85 MB)
__device__ float g_ACL[BB*PP*DD];

// ---------------- K0a: bg, sum g^2, sum bg^2 ----------------
__global__ __launch_bounds__(64) void k_prep(const float* __restrict__ gi,
                                             const float* __restrict__ mk) {
    int bp = blockIdx.x;           // 0..BB*PP-1
    int ch = threadIdx.x;          // 0..63
    float m = mk[bp];
    float g = gi[bp*DD + ch];
    g_bg[bp*DD + ch] = g * m;
    float s = g * g;
    #pragma unroll
    for (int o = 16; o > 0; o >>= 1) s += __shfl_down_sync(0xffffffffu, s, o);
    __shared__ float sh[2];
    if ((ch & 31) == 0) sh[ch >> 5] = s;
    __syncthreads();
    if (ch == 0) {
        float t = sh[0] + sh[1];
        g_sg[bp]  = t;
        g_sbg[bp] = t * m * m;
    }
}

// ---------------- K0b: wwd (3x3 padded box-sum of sg), k1d (box-sum of sbg at interior) ---
__global__ __launch_bounds__(256) void k_stats() {
    int idx = blockIdx.x * 256 + threadIdx.x;
    if (idx < BB*PP) {
        int b = idx / PP, p = idx % PP, py = p / WW, px = p % WW;
        float wv = 0.f;
        #pragma unroll
        for (int oy = -1; oy <= 1; oy++)
            #pragma unroll
            for (int ox = -1; ox <= 1; ox++) {
                int y = py + oy, x = px + ox;
                if ((unsigned)y < HH && (unsigned)x < WW) wv += g_sg[b*PP + y*WW + x];
            }
        g_wwd[idx] = wv;
    }
    if (idx < BB*NJ) {
        int b = idx / NJ, j = idx % NJ;
        int jy = j / CI + 1, jx = j % CI + 1;
        float kv = 0.f;
        #pragma unroll
        for (int oy = -1; oy <= 1; oy++)
            #pragma unroll
            for (int ox = -1; ox <= 1; ox++)
                kv += g_sbg[b*PP + (jy+oy)*WW + (jx+ox)];
        g_k1d[idx] = kv;
    }
}

// ---------------- K1: C0[b,q,p] = sum_ch g_in[b,q,ch]*bg[b,p,ch]  (A.B^T, K=64) ------
__global__ __launch_bounds__(256) void k_c0(const float* __restrict__ gi) {
    int b  = blockIdx.z;
    int q0 = blockIdx.y * 64;
    int p0 = blockIdx.x * 64;
    const float* A = gi   + (size_t)b*PP*DD;
    const float* Bv = g_bg + (size_t)b*PP*DD;
    __shared__ float As[64][65];   // [ch][row]  transposed
    __shared__ float Bs[64][65];
    int tid = threadIdx.x;
    #pragma unroll
    for (int i = 0; i < 16; i++) {
        int idx = tid + i*256;
        int row = idx >> 6, ch = idx & 63;
        As[ch][row] = A [(q0+row)*DD + ch];
        Bs[ch][row] = Bv[(p0+row)*DD + ch];
    }
    __syncthreads();
    int ty = tid >> 4, tx = tid & 15;
    float acc[4][4] = {};
    #pragma unroll
    for (int k = 0; k < 64; k++) {
        float a0 = As[k][ty*4+0], a1 = As[k][ty*4+1], a2 = As[k][ty*4+2], a3 = As[k][ty*4+3];
        float b0 = Bs[k][tx*4+0], b1 = Bs[k][tx*4+1], b2 = Bs[k][tx*4+2], b3 = Bs[k][tx*4+3];
        acc[0][0] += a0*b0; acc[0][1] += a0*b1; acc[0][2] += a0*b2; acc[0][3] += a0*b3;
        acc[1][0] += a1*b0; acc[1][1] += a1*b1; acc[1][2] += a1*b2; acc[1][3] += a1*b3;
        acc[2][0] += a2*b0; acc[2][1] += a2*b1; acc[2][2] += a2*b2; acc[2][3] += a2*b3;
        acc[3][0] += a3*b0; acc[3][1] += a3*b1; acc[3][2] += a3*b2; acc[3][3] += a3*b3;
    }
    float* C = g_C0 + (size_t)b*PP*PP;
    #pragma unroll
    for (int i = 0; i < 4; i++) {
        size_t ro = (size_t)(q0 + ty*4 + i) * PP + p0 + tx*4;
        #pragma unroll
        for (int jj = 0; jj < 4; jj++) C[ro + jj] = acc[i][jj];
    }
}

// ---------------- block reduction helpers (256 threads) ----------------
__device__ __forceinline__ double brsumd(double v, double* sh) {
    #pragma unroll
    for (int o = 16; o > 0; o >>= 1) v += __shfl_down_sync(0xffffffffu, v, o);
    int lane = threadIdx.x & 31, w = threadIdx.x >> 5;
    if (lane == 0) sh[w] = v;
    __syncthreads();
    if (threadIdx.x < 32) {
        v = (lane < 8) ? sh[lane] : 0.0;
        #pragma unroll
        for (int o = 4; o > 0; o >>= 1) v += __shfl_down_sync(0xffffffffu, v, o);
        if (lane == 0) sh[0] = v;
    }
    __syncthreads();
    double r = sh[0];
    __syncthreads();
    return r;
}
__device__ __forceinline__ float brsumf(float v, float* sh) {
    #pragma unroll
    for (int o = 16; o > 0; o >>= 1) v += __shfl_down_sync(0xffffffffu, v, o);
    int lane = threadIdx.x & 31, w = threadIdx.x >> 5;
    if (lane == 0) sh[w] = v;
    __syncthreads();
    if (threadIdx.x < 32) {
        v = (lane < 8) ? sh[lane] : 0.f;
        #pragma unroll
        for (int o = 4; o > 0; o >>= 1) v += __shfl_down_sync(0xffffffffu, v, o);
        if (lane == 0) sh[0] = v;
    }
    __syncthreads();
    float r = sh[0];
    __syncthreads();
    return r;
}
__device__ __forceinline__ float brmaxf(float v, float* sh) {
    #pragma unroll
    for (int o = 16; o > 0; o >>= 1) v = fmaxf(v, __shfl_down_sync(0xffffffffu, v, o));
    int lane = threadIdx.x & 31, w = threadIdx.x >> 5;
    if (lane == 0) sh[w] = v;
    __syncthreads();
    if (threadIdx.x < 32) {
        v = (lane < 8) ? sh[lane] : -3.4e38f;
        #pragma unroll
        for (int o = 4; o > 0; o >>= 1) v = fmaxf(v, __shfl_down_sync(0xffffffffu, v, o));
        if (lane == 0) sh[0] = v;
    }
    __syncthreads();
    float r = sh[0];
    __syncthreads();
    return r;
}

// ---------------- K2: fused DS1 -> normalize -> tanh -> softmax -> CA -----------
// one block per (b, q); CS via 9-tap diagonal box-sum over C0 rows.
__global__ __launch_bounds__(256) void k_attn() {
    __shared__ double shd[8];
    __shared__ float  shf[8];
    int bq = blockIdx.x;
    int b = bq / PP, q = bq % PP;
    int qy = q / WW, qx = q % WW;
    const float* __restrict__ C0b = g_C0 + (size_t)b*PP*PP;
    const float* __restrict__ k1  = g_k1d + b*NJ;
    float wv = g_wwd[bq];

    const float* base[9];
    bool bval[9];
    {
        int oidx = 0;
        #pragma unroll
        for (int oy = -1; oy <= 1; oy++)
            #pragma unroll
            for (int ox = -1; ox <= 1; ox++, oidx++) {
                int yy = qy + oy, xx = qx + ox;
                bval[oidx] = ((unsigned)yy < HH) && ((unsigned)xx < WW);
                base[oidx] = C0b + (size_t)(yy*WW + xx)*PP + (oy*WW + ox);
            }
    }

    int tid = threadIdx.x;
    float ds[9];
    #pragma unroll
    for (int t = 0; t < 9; t++) {
        int j = tid + t*256;
        float val = 0.f;
        if (j < NJ) {
            int jy = j / CI, jx = j % CI;
            int c = (jy+1)*WW + (jx+1);
            float cs = 0.f;
            #pragma unroll
            for (int o = 0; o < 9; o++)
                if (bval[o]) cs += base[o][c];
            val = k1[j] + wv - 2.f*cs;
        }
        ds[t] = val;
    }

    // pass 1: mean (double for safety, TEMP=50 amplifies logit error)
    double lsum = 0.0;
    #pragma unroll
    for (int t = 0; t < 9; t++) if (tid + t*256 < NJ) lsum += (double)ds[t];
    double tot = brsumd(lsum, shd);
    float mu = (float)(tot / (double)NJ);

    // pass 2: variance
    double lss = 0.0;
    #pragma unroll
    for (int t = 0; t < 9; t++)
        if (tid + t*256 < NJ) { double d = (double)ds[t] - (double)mu; lss += d*d; }
    double vtot = brsumd(lss, shd);
    float sd = (float)sqrt(vtot / (double)NJ);
    float inv = 1.f / sd;

    // logits + softmax
    float lmax = -3.4e38f;
    #pragma unroll
    for (int t = 0; t < 9; t++) {
        if (tid + t*256 < NJ) {
            float lg = -tanhf((ds[t] - mu) * inv) * TEMPF;
            ds[t] = lg;
            lmax = fmaxf(lmax, lg);
        }
    }
    float gmax = brmaxf(lmax, shf);
    float lse = 0.f;
    #pragma unroll
    for (int t = 0; t < 9; t++) {
        if (tid + t*256 < NJ) {
            float e = __expf(ds[t] - gmax);
            ds[t] = e;
            lse += e;
        }
    }
    float tote = brsumf(lse, shf);
    float invs = 1.f / tote;
    float* CArow = g_CA + (size_t)bq*NJ;
    #pragma unroll
    for (int t = 0; t < 9; t++) {
        int j = tid + t*256;
        if (j < NJ) CArow[j] = ds[t] * invs;
    }
}

// ---------------- K3: E[r,p] = sum_o CA_scatter[r-o, p-o] -----------------------
__global__ __launch_bounds__(256) void k_ebuild() {
    int br = blockIdx.x;
    int b = br / PP, r = br % PP;
    int ry = r / WW, rx = r % WW;
    const float* __restrict__ CAb = g_CA + (size_t)b*PP*NJ;
    float* __restrict__ Erow = g_E + (size_t)br*PP;

    const float* rbase[9];
    bool rv[9];
    {
        int oidx = 0;
        #pragma unroll
        for (int oy = -1; oy <= 1; oy++)
            #pragma unroll
            for (int ox = -1; ox <= 1; ox++, oidx++) {
                int sy = ry - oy, sx = rx - ox;
                rv[oidx] = ((unsigned)sy < HH) && ((unsigned)sx < WW);
                rbase[oidx] = CAb + (size_t)(sy*WW + sx)*NJ;
            }
    }
    for (int p = threadIdx.x; p < PP; p += 256) {
        int py = p / WW, px = p % WW;
        float e = 0.f;
        int oidx = 0;
        #pragma unroll
        for (int oy = -1; oy <= 1; oy++)
            #pragma unroll
            for (int ox = -1; ox <= 1; ox++, oidx++) {
                int ty = py - oy - 1, tx = px - ox - 1;  // candidate-grid coords
                if (rv[oidx] && (unsigned)ty < CI && (unsigned)tx < CI)
                    e += rbase[oidx][ty*CI + tx];
            }
        Erow[p] = e;
    }
}

// ---------------- K4: acl = (1/9) E.bg ; ACL = bg + acl*(1-mask) ----------------
__global__ __launch_bounds__(256) void k_acl(const float* __restrict__ mk) {
    int b  = blockIdx.y;
    int r0 = blockIdx.x * 64;
    const float* Eb = g_E  + (size_t)b*PP*PP;
    const float* Bb = g_bg + (size_t)b*PP*DD;
    __shared__ float Es[64][65];   // [kk][m]
    __shared__ float Bs[64][65];   // [kk][n]
    int tid = threadIdx.x;
    int ty = tid >> 4, tx = tid & 15;
    float acc[4][4] = {};
    for (int k0 = 0; k0 < PP; k0 += 64) {
        #pragma unroll
        for (int i = 0; i < 16; i++) {
            int idx = tid + i*256;
            int m = idx >> 6, kk = idx & 63;
            Es[kk][m] = Eb[(size_t)(r0+m)*PP + k0 + kk];
            Bs[m][kk] = Bb[(size_t)(k0+m)*DD + kk];   // m plays role of kk here
        }
        __syncthreads();
        #pragma unroll
        for (int kk = 0; kk < 64; kk++) {
            float a0 = Es[kk][ty*4+0], a1 = Es[kk][ty*4+1], a2 = Es[kk][ty*4+2], a3 = Es[kk][ty*4+3];
            float b0 = Bs[kk][tx*4+0], b1 = Bs[kk][tx*4+1], b2 = Bs[kk][tx*4+2], b3 = Bs[kk][tx*4+3];
            acc[0][0] += a0*b0; acc[0][1] += a0*b1; acc[0][2] += a0*b2; acc[0][3] += a0*b3;
            acc[1][0] += a1*b0; acc[1][1] += a1*b1; acc[1][2] += a1*b2; acc[1][3] += a1*b3;
            acc[2][0] += a2*b0; acc[2][1] += a2*b1; acc[2][2] += a2*b2; acc[2][3] += a2*b3;
            acc[3][0] += a3*b0; acc[3][1] += a3*b1; acc[3][2] += a3*b2; acc[3][3] += a3*b3;
        }
        __syncthreads();
    }
    const float ninth = 1.f / 9.f;
    #pragma unroll
    for (int i = 0; i < 4; i++) {
        int r = r0 + ty*4 + i;
        float m  = mk[b*PP + r];
        float om = 1.f - m;
        #pragma unroll
        for (int jj = 0; jj < 4; jj++) {
            int d = tx*4 + jj;
            float bgv = Bb[(size_t)r*DD + d];
            g_ACL[(size_t)(b*PP + r)*DD + d] = bgv + acc[i][jj]*ninth*om;
        }
    }
}

// ---------------- K5: out = elu(concat(g_in, ACL) @ W2 + b2) --------------------
__global__ __launch_bounds__(256) void k_out(const float* __restrict__ gi,
                                             const float* __restrict__ W2,
                                             const float* __restrict__ b2,
                                             float* __restrict__ out) {
    int blk = blockIdx.x;          // 4 pixels per block
    int tid = threadIdx.x;
    int pl = tid >> 6, d = tid & 63;
    __shared__ float row[4][128];
    for (int i = tid; i < 512; i += 256) {
        int rr = i >> 7, k = i & 127;
        int gp = blk*4 + rr;
        row[rr][k] = (k < 64) ? gi[gp*DD + k] : g_ACL[gp*DD + (k - 64)];
    }
    __syncthreads();
    int bp = blk*4 + pl;
    float acc = b2[d];
    #pragma unroll 8
    for (int k = 0; k < 128; k++) acc += row[pl][k] * W2[k*64 + d];
    out[bp*DD + d] = (acc > 0.f) ? acc : expm1f(acc);
}

// ---------------- launcher ----------------
extern "C" void kernel_launch(void* const* d_in, const int* in_sizes, int n_in,
                              void* d_out, int out_size) {
    const float* g_in = (const float*)d_in[0];
    const float* mask = (const float*)d_in[1];
    const float* W2   = (const float*)d_in[2];
    const float* b2   = (const float*)d_in[3];
    float* out = (float*)d_out;

    k_prep  <<<BB*PP, 64>>>(g_in, mask);
    k_stats <<<(BB*PP + 255)/256, 256>>>();
    k_c0    <<<dim3(PP/64, PP/64, BB), 256>>>(g_in);
    k_attn  <<<BB*PP, 256>>>();
    k_ebuild<<<BB*PP, 256>>>();
    k_acl   <<<dim3(PP/64, BB), 256>>>(mask);
    k_out   <<<BB*PP/4, 256>>>(g_in, W2, b2, out);
}